// round 1
// baseline (speedup 1.0000x reference)
#include <cuda_runtime.h>
#include <cstdint>

// Problem constants (fixed by the dataset)
#define NNODES 100000
#define DDIM   128
#define RREL   3
#define EEDGES 500000
#define NBASIS 2

// GEMM tiling
#define BM 128
#define BN 128
#define BK 16

// ---------------- scratch (device globals; no allocation allowed) ----------
__device__ float g_h0[(size_t)NNODES * DDIM];                 // 51.2 MB
__device__ float g_h1[(size_t)NNODES * DDIM];                 // 51.2 MB
__device__ float g_agg[(size_t)RREL * NNODES * DDIM];         // 153.6 MB
__device__ float g_rdeg[(size_t)RREL * NNODES];
__device__ int   g_deg [(size_t)RREL * NNODES];
__device__ float g_wst[4 * DDIM * DDIM];                      // stacked weights

// ---------------- small utility kernels ------------------------------------
__global__ void zero_int_kernel(int* p, int n) {
    int i = blockIdx.x * blockDim.x + threadIdx.x;
    if (i < n) p[i] = 0;
}

__global__ void zero_f4_kernel(float4* p, size_t n4) {
    size_t i = (size_t)blockIdx.x * blockDim.x + threadIdx.x;
    size_t stride = (size_t)gridDim.x * blockDim.x;
    float4 z = make_float4(0.f, 0.f, 0.f, 0.f);
    for (; i < n4; i += stride) p[i] = z;
}

__global__ void deg_count_kernel(const int* __restrict__ dst, int* __restrict__ deg) {
    int i = blockIdx.x * blockDim.x + threadIdx.x;
    if (i >= RREL * EEDGES) return;
    int r = i / EEDGES;
    atomicAdd(&deg[r * NNODES + dst[i]], 1);
}

__global__ void make_rdeg_kernel(const int* __restrict__ deg, float* __restrict__ rdeg) {
    int i = blockIdx.x * blockDim.x + threadIdx.x;
    if (i >= RREL * NNODES) return;
    rdeg[i] = 1.0f / fmaxf((float)deg[i], 1.0f);
}

// Build stacked weights: segments 0..2 = sum_b coeff[r,b]*basis[b], segment 3 = loop_w
__global__ void build_w_kernel(const float* __restrict__ basis,
                               const float* __restrict__ coeff,
                               const float* __restrict__ loopw,
                               float* __restrict__ wst) {
    int i = blockIdx.x * blockDim.x + threadIdx.x;   // 4 * D*D = 65536
    if (i >= 4 * DDIM * DDIM) return;
    int t = i >> 14;                 // D*D = 16384 = 2^14
    int j = i & (DDIM * DDIM - 1);
    float v;
    if (t < 3)
        v = coeff[t * NBASIS + 0] * basis[j] + coeff[t * NBASIS + 1] * basis[DDIM * DDIM + j];
    else
        v = loopw[j];
    wst[i] = v;
}

// ---------------- scatter-aggregate: one warp per edge ---------------------
// agg[r, dst, :] += rdeg[r, dst] * h[src, :]
__global__ void scatter_kernel(const float* __restrict__ h,
                               const int*   __restrict__ src,
                               const int*   __restrict__ dst,
                               const float* __restrict__ rdeg,
                               float* __restrict__ agg) {
    unsigned gw = ((unsigned)blockIdx.x * 256u + threadIdx.x) >> 5;
    int lane = threadIdx.x & 31;
    if (gw >= (unsigned)(RREL * EEDGES)) return;
    int r = (int)(gw / EEDGES);
    int s = __ldg(src + gw);
    int d = __ldg(dst + gw);
    float w = __ldg(rdeg + (size_t)r * NNODES + d);
    float4 v = *reinterpret_cast<const float4*>(h + (size_t)s * DDIM + lane * 4);
    float* p = agg + ((size_t)r * NNODES + d) * DDIM + lane * 4;
    asm volatile("red.global.add.v4.f32 [%0], {%1,%2,%3,%4};"
                 :: "l"(p), "f"(v.x * w), "f"(v.y * w), "f"(v.z * w), "f"(v.w * w)
                 : "memory");
}

// ---------------- concatenated GEMM ----------------------------------------
// C[n, o] = act( sum_{s<NSEG} sum_k Aseg[s][n, k] * Bw[s*D + k, o] + bias[o] )
// 128x128 block tile, 256 threads, 8x8 microtile, BK=16.
template <bool RELU, int NSEG>
__global__ __launch_bounds__(256, 2)
void gemm_kernel(const float* __restrict__ A0, const float* __restrict__ A1,
                 const float* __restrict__ A2, const float* __restrict__ A3,
                 const float* __restrict__ Bw, const float* __restrict__ bias,
                 float* __restrict__ C, int nrows) {
    __shared__ float As[BK][BM];
    __shared__ float Bs[BK][BN];

    const float* Aseg[4] = {A0, A1, A2, A3};
    int tid = threadIdx.x;
    int tx = tid & 15;       // output column group
    int ty = tid >> 4;       // output row group
    int n0 = blockIdx.x * BM;

    float acc[8][8];
#pragma unroll
    for (int i = 0; i < 8; i++)
#pragma unroll
        for (int j = 0; j < 8; j++) acc[i][j] = 0.f;

#pragma unroll
    for (int s = 0; s < NSEG; ++s) {
        const float* A = Aseg[s];
#pragma unroll 1
        for (int kt = 0; kt < DDIM / BK; ++kt) {
            // load A tile (128 rows x 16 cols), transposed into As[k][m]
#pragma unroll
            for (int i = 0; i < 2; ++i) {
                int lin = tid + i * 256;         // 0..511
                int m = lin >> 2;
                int q = lin & 3;
                float4 v = make_float4(0.f, 0.f, 0.f, 0.f);
                int n = n0 + m;
                if (n < nrows)
                    v = *reinterpret_cast<const float4*>(A + (size_t)n * DDIM + kt * BK + q * 4);
                As[q * 4 + 0][m] = v.x;
                As[q * 4 + 1][m] = v.y;
                As[q * 4 + 2][m] = v.z;
                As[q * 4 + 3][m] = v.w;
            }
            // load B tile (16 rows x 128 cols)
#pragma unroll
            for (int i = 0; i < 2; ++i) {
                int lin = tid + i * 256;
                int k = lin >> 5;
                int c4 = lin & 31;
                *reinterpret_cast<float4*>(&Bs[k][c4 * 4]) =
                    *reinterpret_cast<const float4*>(Bw + (size_t)(s * DDIM + kt * BK + k) * DDIM + c4 * 4);
            }
            __syncthreads();
#pragma unroll
            for (int k = 0; k < BK; ++k) {
                float ar[8], br[8];
                *reinterpret_cast<float4*>(&ar[0]) = *reinterpret_cast<float4*>(&As[k][ty * 8]);
                *reinterpret_cast<float4*>(&ar[4]) = *reinterpret_cast<float4*>(&As[k][ty * 8 + 4]);
                *reinterpret_cast<float4*>(&br[0]) = *reinterpret_cast<float4*>(&Bs[k][tx * 8]);
                *reinterpret_cast<float4*>(&br[4]) = *reinterpret_cast<float4*>(&Bs[k][tx * 8 + 4]);
#pragma unroll
                for (int i = 0; i < 8; i++)
#pragma unroll
                    for (int j = 0; j < 8; j++)
                        acc[i][j] += ar[i] * br[j];
            }
            __syncthreads();
        }
    }

    float bz[8];
#pragma unroll
    for (int j = 0; j < 8; j++) bz[j] = bias[tx * 8 + j];

#pragma unroll
    for (int i = 0; i < 8; i++) {
        int n = n0 + ty * 8 + i;
        if (n < nrows) {
            float o[8];
#pragma unroll
            for (int j = 0; j < 8; j++) {
                float v = acc[i][j] + bz[j];
                o[j] = RELU ? fmaxf(v, 0.f) : v;
            }
            *reinterpret_cast<float4*>(C + (size_t)n * DDIM + tx * 8) =
                *reinterpret_cast<float4*>(&o[0]);
            *reinterpret_cast<float4*>(C + (size_t)n * DDIM + tx * 8 + 4) =
                *reinterpret_cast<float4*>(&o[4]);
        }
    }
}

// ---------------- launch -----------------------------------------------------
extern "C" void kernel_launch(void* const* d_in, const int* in_sizes, int n_in,
                              void* d_out, int out_size) {
    const float* x        = (const float*)d_in[0];
    const int*   edge_src = (const int*)  d_in[1];
    const int*   edge_dst = (const int*)  d_in[2];
    const float* proj_w   = (const float*)d_in[3];
    const float* proj_b   = (const float*)d_in[4];
    const float* basis1   = (const float*)d_in[5];
    const float* coeff1   = (const float*)d_in[6];
    const float* bias1    = (const float*)d_in[7];
    const float* loop1    = (const float*)d_in[8];
    const float* basis2   = (const float*)d_in[9];
    const float* coeff2   = (const float*)d_in[10];
    const float* bias2    = (const float*)d_in[11];
    const float* loop2    = (const float*)d_in[12];
    float* out = (float*)d_out;

    float *h0, *h1, *agg, *rdeg, *wst;
    int* deg;
    cudaGetSymbolAddress((void**)&h0,   g_h0);
    cudaGetSymbolAddress((void**)&h1,   g_h1);
    cudaGetSymbolAddress((void**)&agg,  g_agg);
    cudaGetSymbolAddress((void**)&rdeg, g_rdeg);
    cudaGetSymbolAddress((void**)&deg,  g_deg);
    cudaGetSymbolAddress((void**)&wst,  g_wst);

    const int grid_n    = (NNODES + BM - 1) / BM;                 // 782
    const int rn        = RREL * NNODES;
    const int re        = RREL * EEDGES;
    const int scat_blk  = (re * 32 + 255) / 256;                  // one warp per edge
    const size_t agg_f4 = (size_t)RREL * NNODES * DDIM / 4;

    // degrees (topology-only: once, reused by both layers)
    zero_int_kernel<<<(rn + 255) / 256, 256>>>(deg, rn);
    deg_count_kernel<<<(re + 255) / 256, 256>>>(edge_dst, deg);
    make_rdeg_kernel<<<(rn + 255) / 256, 256>>>(deg, rdeg);

    // projection: h0 = x @ proj_w + proj_b
    gemm_kernel<false, 1><<<grid_n, 256>>>(x, x, x, x, proj_w, proj_b, h0, NNODES);

    // ---- layer 1 ----
    build_w_kernel<<<(4 * DDIM * DDIM + 255) / 256, 256>>>(basis1, coeff1, loop1, wst);
    zero_f4_kernel<<<4096, 256>>>((float4*)agg, agg_f4);
    scatter_kernel<<<scat_blk, 256>>>(h0, edge_src, edge_dst, rdeg, agg);
    gemm_kernel<true, 4><<<grid_n, 256>>>(agg,
                                          agg + (size_t)NNODES * DDIM,
                                          agg + 2 * (size_t)NNODES * DDIM,
                                          h0, wst, bias1, h1, NNODES);

    // ---- layer 2 ----
    build_w_kernel<<<(4 * DDIM * DDIM + 255) / 256, 256>>>(basis2, coeff2, loop2, wst);
    zero_f4_kernel<<<4096, 256>>>((float4*)agg, agg_f4);
    scatter_kernel<<<scat_blk, 256>>>(h1, edge_src, edge_dst, rdeg, agg);
    gemm_kernel<true, 4><<<grid_n, 256>>>(agg,
                                          agg + (size_t)NNODES * DDIM,
                                          agg + 2 * (size_t)NNODES * DDIM,
                                          h1, wst, bias2, out, NNODES);
}

// round 3
// speedup vs baseline: 1.3119x; 1.3119x over previous
#include <cuda_runtime.h>
#include <cuda_bf16.h>
#include <cstdint>

// Problem constants
#define NNODES 100000
#define DDIM   128
#define RREL   3
#define EEDGES 500000
#define NBASIS 2

// ---------------- scratch (device globals) ----------------------------------
__device__ float g_h0[(size_t)NNODES * DDIM];
__device__ float g_h1[(size_t)NNODES * DDIM];
__device__ float g_agg[(size_t)RREL * NNODES * DDIM];
__device__ float g_rdeg[(size_t)RREL * NNODES];
__device__ int   g_deg [(size_t)RREL * NNODES];
__device__ __nv_bfloat16 g_wthi[128 * 512];   // layer weights, [o][k], hi part
__device__ __nv_bfloat16 g_wtlo[128 * 512];   // lo part
__device__ __nv_bfloat16 g_pwhi[128 * 128];   // proj weights [o][k], hi
__device__ __nv_bfloat16 g_pwlo[128 * 128];   // lo

// ---------------- smem layout for the GEMM -----------------------------------
// bf16 tiles, 128 rows x 64 cols, row pitch 72 bf16 (144B = 36 banks -> LDS
// fragment loads are conflict-free: bank = (4*g + tg) % 32 covers all banks).
#define PITCH_B 144
#define TILE_BYTES (128 * PITCH_B)          // 18432
#define OFF_AHI 0
#define OFF_ALO (TILE_BYTES)
#define OFF_BHI (2 * TILE_BYTES)
#define OFF_BLO (3 * TILE_BYTES)
#define GEMM_SMEM (4 * TILE_BYTES)          // 73728

__device__ __forceinline__ void mma16816(float* c, const uint32_t* a, const uint32_t* b) {
    asm volatile(
        "mma.sync.aligned.m16n8k16.row.col.f32.bf16.bf16.f32 "
        "{%0,%1,%2,%3}, {%4,%5,%6,%7}, {%8,%9}, {%0,%1,%2,%3};\n"
        : "+f"(c[0]), "+f"(c[1]), "+f"(c[2]), "+f"(c[3])
        : "r"(a[0]), "r"(a[1]), "r"(a[2]), "r"(a[3]), "r"(b[0]), "r"(b[1]));
}

// ---------------- split-bf16 tensor-core GEMM (mma.sync) ----------------------
// C[n,o] = act( sum_s sum_k A_s[n,k] * W[s*128+k, o] + bias[o] )
// whi/wlo: [o][KSTRIDE] bf16 (pre-transposed + split), KSTRIDE = NSEG*128.
template <bool RELU, int NSEG>
__global__ __launch_bounds__(256, 2)
void tc_gemm(const float* __restrict__ A0, const float* __restrict__ A1,
             const float* __restrict__ A2, const float* __restrict__ A3,
             const __nv_bfloat16* __restrict__ whi, const __nv_bfloat16* __restrict__ wlo,
             const float* __restrict__ bias, float* __restrict__ C, int nrows) {
    extern __shared__ char smem[];
    const int tid  = threadIdx.x;
    const int wid  = tid >> 5;
    const int lane = tid & 31;
    const int wm = wid & 3;          // warp row  (4)  -> 32 rows each
    const int wn = wid >> 2;         // warp col  (2)  -> 64 cols each
    const int g  = lane >> 2;        // 0..7
    const int tg = lane & 3;         // 0..3
    const int n0 = blockIdx.x * 128;
    const int KSTRIDE = NSEG * 128;
    const float* Aseg[4] = {A0, A1, A2, A3};

    float acc[2][8][4];
#pragma unroll
    for (int mt = 0; mt < 2; mt++)
#pragma unroll
        for (int nt = 0; nt < 8; nt++)
#pragma unroll
            for (int j = 0; j < 4; j++) acc[mt][nt][j] = 0.f;

    const int arow = (wm * 32 + g) * PITCH_B + tg * 4;   // byte offset, A frag base
    const int brow = (wn * 64 + g) * PITCH_B + tg * 4;   // byte offset, B frag base

    const int NCHUNK = 2 * NSEG;
#pragma unroll 1
    for (int c = 0; c < NCHUNK; ++c) {
        const float* A = Aseg[c >> 1];
        const int kc = (c & 1) * 64;

        // ---- A chunk [128 x 64] fp32 -> split bf16 hi/lo into smem ----
#pragma unroll
        for (int i = 0; i < 8; ++i) {
            int idx = i * 256 + tid;          // 0..2047 float4 slots
            int row = idx >> 4;               // 16 float4 per row
            int q   = idx & 15;               // col4 index
            int n = n0 + row;
            float4 v = make_float4(0.f, 0.f, 0.f, 0.f);
            if (n < nrows)
                v = *reinterpret_cast<const float4*>(A + (size_t)n * DDIM + kc + q * 4);
            __nv_bfloat16 h0 = __float2bfloat16(v.x), h1 = __float2bfloat16(v.y);
            __nv_bfloat16 h2 = __float2bfloat16(v.z), h3 = __float2bfloat16(v.w);
            __nv_bfloat16 l0 = __float2bfloat16(v.x - __bfloat162float(h0));
            __nv_bfloat16 l1 = __float2bfloat16(v.y - __bfloat162float(h1));
            __nv_bfloat16 l2 = __float2bfloat16(v.z - __bfloat162float(h2));
            __nv_bfloat16 l3 = __float2bfloat16(v.w - __bfloat162float(h3));
            int boff = row * PITCH_B + q * 8;
            *reinterpret_cast<__nv_bfloat162*>(smem + OFF_AHI + boff)     = __nv_bfloat162(h0, h1);
            *reinterpret_cast<__nv_bfloat162*>(smem + OFF_AHI + boff + 4) = __nv_bfloat162(h2, h3);
            *reinterpret_cast<__nv_bfloat162*>(smem + OFF_ALO + boff)     = __nv_bfloat162(l0, l1);
            *reinterpret_cast<__nv_bfloat162*>(smem + OFF_ALO + boff + 4) = __nv_bfloat162(l2, l3);
        }

        // ---- B chunk [128 o x 64 k] bf16 hi/lo into smem ----
#pragma unroll
        for (int i = 0; i < 4; ++i) {
            int idx = i * 256 + tid;          // 0..1023 uint4 slots
            int n = idx >> 3;                 // 8 uint4 per row
            int q = idx & 7;
            int boff = n * PITCH_B + q * 16;
            size_t goff = (size_t)n * KSTRIDE + c * 64 + q * 8;
            *reinterpret_cast<uint4*>(smem + OFF_BHI + boff) =
                *reinterpret_cast<const uint4*>(whi + goff);
            *reinterpret_cast<uint4*>(smem + OFF_BLO + boff) =
                *reinterpret_cast<const uint4*>(wlo + goff);
        }
        __syncthreads();

        // ---- compute: 4 k16-steps x 3 split products ----
#pragma unroll
        for (int ks = 0; ks < 4; ++ks) {
            const int kb = ks * 32;           // k byte offset
            uint32_t ahi[2][4], alo[2][4], bfr[8][2];
#pragma unroll
            for (int mt = 0; mt < 2; ++mt) {
                int base = arow + mt * (16 * PITCH_B) + kb;
                ahi[mt][0] = *(const uint32_t*)(smem + OFF_AHI + base);
                ahi[mt][1] = *(const uint32_t*)(smem + OFF_AHI + base + 8 * PITCH_B);
                ahi[mt][2] = *(const uint32_t*)(smem + OFF_AHI + base + 16);
                ahi[mt][3] = *(const uint32_t*)(smem + OFF_AHI + base + 8 * PITCH_B + 16);
                alo[mt][0] = *(const uint32_t*)(smem + OFF_ALO + base);
                alo[mt][1] = *(const uint32_t*)(smem + OFF_ALO + base + 8 * PITCH_B);
                alo[mt][2] = *(const uint32_t*)(smem + OFF_ALO + base + 16);
                alo[mt][3] = *(const uint32_t*)(smem + OFF_ALO + base + 8 * PITCH_B + 16);
            }
#pragma unroll
            for (int nt = 0; nt < 8; ++nt) {
                int bb = brow + nt * (8 * PITCH_B) + kb;
                bfr[nt][0] = *(const uint32_t*)(smem + OFF_BHI + bb);
                bfr[nt][1] = *(const uint32_t*)(smem + OFF_BHI + bb + 16);
            }
#pragma unroll
            for (int mt = 0; mt < 2; ++mt)
#pragma unroll
                for (int nt = 0; nt < 8; ++nt) {
                    mma16816(acc[mt][nt], ahi[mt], bfr[nt]);   // hi*hi
                    mma16816(acc[mt][nt], alo[mt], bfr[nt]);   // lo*hi
                }
#pragma unroll
            for (int nt = 0; nt < 8; ++nt) {
                int bb = brow + nt * (8 * PITCH_B) + kb;
                bfr[nt][0] = *(const uint32_t*)(smem + OFF_BLO + bb);
                bfr[nt][1] = *(const uint32_t*)(smem + OFF_BLO + bb + 16);
            }
#pragma unroll
            for (int mt = 0; mt < 2; ++mt)
#pragma unroll
                for (int nt = 0; nt < 8; ++nt)
                    mma16816(acc[mt][nt], ahi[mt], bfr[nt]);   // hi*lo
        }
        __syncthreads();
    }

    // ---- epilogue: bias + relu, float2 stores ----
#pragma unroll
    for (int nt = 0; nt < 8; ++nt) {
        int col = wn * 64 + nt * 8 + 2 * tg;
        float bz0 = __ldg(bias + col);
        float bz1 = __ldg(bias + col + 1);
#pragma unroll
        for (int mt = 0; mt < 2; ++mt) {
            int row0 = n0 + wm * 32 + mt * 16 + g;
            int row1 = row0 + 8;
            float v0 = acc[mt][nt][0] + bz0, v1 = acc[mt][nt][1] + bz1;
            float v2 = acc[mt][nt][2] + bz0, v3 = acc[mt][nt][3] + bz1;
            if (RELU) {
                v0 = fmaxf(v0, 0.f); v1 = fmaxf(v1, 0.f);
                v2 = fmaxf(v2, 0.f); v3 = fmaxf(v3, 0.f);
            }
            if (row0 < nrows)
                *reinterpret_cast<float2*>(C + (size_t)row0 * DDIM + col) = make_float2(v0, v1);
            if (row1 < nrows)
                *reinterpret_cast<float2*>(C + (size_t)row1 * DDIM + col) = make_float2(v2, v3);
        }
    }
}

// ---------------- small utility kernels --------------------------------------
__global__ void zero_int_kernel(int* p, int n) {
    int i = blockIdx.x * blockDim.x + threadIdx.x;
    if (i < n) p[i] = 0;
}

__global__ void zero_f4_kernel(float4* p, size_t n4) {
    size_t i = (size_t)blockIdx.x * blockDim.x + threadIdx.x;
    size_t stride = (size_t)gridDim.x * blockDim.x;
    float4 z = make_float4(0.f, 0.f, 0.f, 0.f);
    for (; i < n4; i += stride) p[i] = z;
}

__global__ void deg_count_kernel(const int* __restrict__ dst, int* __restrict__ deg) {
    int i = blockIdx.x * blockDim.x + threadIdx.x;
    if (i >= RREL * EEDGES) return;
    int r = i / EEDGES;
    atomicAdd(&deg[r * NNODES + dst[i]], 1);
}

__global__ void make_rdeg_kernel(const int* __restrict__ deg, float* __restrict__ rdeg) {
    int i = blockIdx.x * blockDim.x + threadIdx.x;
    if (i >= RREL * NNODES) return;
    rdeg[i] = 1.0f / fmaxf((float)deg[i], 1.0f);
}

// Build stacked, transposed, bf16-split weights for a layer: wt[o][k], k in [0,512)
__global__ void build_wt_layer(const float* __restrict__ basis, const float* __restrict__ coeff,
                               const float* __restrict__ loopw,
                               __nv_bfloat16* __restrict__ whi, __nv_bfloat16* __restrict__ wlo) {
    int i = blockIdx.x * blockDim.x + threadIdx.x;   // 128*512
    if (i >= 128 * 512) return;
    int o = i >> 9;
    int k = i & 511;
    int seg = k >> 7;
    int kk = k & 127;
    float v;
    if (seg < 3)
        v = coeff[seg * NBASIS + 0] * basis[kk * DDIM + o]
          + coeff[seg * NBASIS + 1] * basis[DDIM * DDIM + kk * DDIM + o];
    else
        v = loopw[kk * DDIM + o];
    __nv_bfloat16 h = __float2bfloat16(v);
    whi[i] = h;
    wlo[i] = __float2bfloat16(v - __bfloat162float(h));
}

__global__ void build_wt_proj(const float* __restrict__ projw,
                              __nv_bfloat16* __restrict__ whi, __nv_bfloat16* __restrict__ wlo) {
    int i = blockIdx.x * blockDim.x + threadIdx.x;   // 128*128
    if (i >= 128 * 128) return;
    int o = i >> 7;
    int k = i & 127;
    float v = projw[k * DDIM + o];
    __nv_bfloat16 h = __float2bfloat16(v);
    whi[i] = h;
    wlo[i] = __float2bfloat16(v - __bfloat162float(h));
}

// ---------------- scatter-aggregate: one warp per edge ------------------------
__global__ void scatter_kernel(const float* __restrict__ h,
                               const int*   __restrict__ src,
                               const int*   __restrict__ dst,
                               const float* __restrict__ rdeg,
                               float* __restrict__ agg) {
    unsigned gw = ((unsigned)blockIdx.x * 256u + threadIdx.x) >> 5;
    int lane = threadIdx.x & 31;
    if (gw >= (unsigned)(RREL * EEDGES)) return;
    int r = (int)(gw / EEDGES);
    int s = __ldg(src + gw);
    int d = __ldg(dst + gw);
    float w = __ldg(rdeg + (size_t)r * NNODES + d);
    float4 v = *reinterpret_cast<const float4*>(h + (size_t)s * DDIM + lane * 4);
    float* p = agg + ((size_t)r * NNODES + d) * DDIM + lane * 4;
    asm volatile("red.global.add.v4.f32 [%0], {%1,%2,%3,%4};"
                 :: "l"(p), "f"(v.x * w), "f"(v.y * w), "f"(v.z * w), "f"(v.w * w)
                 : "memory");
}

// ---------------- launch -------------------------------------------------------
extern "C" void kernel_launch(void* const* d_in, const int* in_sizes, int n_in,
                              void* d_out, int out_size) {
    const float* x        = (const float*)d_in[0];
    const int*   edge_src = (const int*)  d_in[1];
    const int*   edge_dst = (const int*)  d_in[2];
    const float* proj_w   = (const float*)d_in[3];
    const float* proj_b   = (const float*)d_in[4];
    const float* basis1   = (const float*)d_in[5];
    const float* coeff1   = (const float*)d_in[6];
    const float* bias1    = (const float*)d_in[7];
    const float* loop1    = (const float*)d_in[8];
    const float* basis2   = (const float*)d_in[9];
    const float* coeff2   = (const float*)d_in[10];
    const float* bias2    = (const float*)d_in[11];
    const float* loop2    = (const float*)d_in[12];
    float* out = (float*)d_out;

    float *h0, *h1, *agg, *rdeg;
    int* deg;
    __nv_bfloat16 *wthi, *wtlo, *pwhi, *pwlo;
    cudaGetSymbolAddress((void**)&h0,   g_h0);
    cudaGetSymbolAddress((void**)&h1,   g_h1);
    cudaGetSymbolAddress((void**)&agg,  g_agg);
    cudaGetSymbolAddress((void**)&rdeg, g_rdeg);
    cudaGetSymbolAddress((void**)&deg,  g_deg);
    cudaGetSymbolAddress((void**)&wthi, g_wthi);
    cudaGetSymbolAddress((void**)&wtlo, g_wtlo);
    cudaGetSymbolAddress((void**)&pwhi, g_pwhi);
    cudaGetSymbolAddress((void**)&pwlo, g_pwlo);

    cudaFuncSetAttribute(tc_gemm<false, 1>, cudaFuncAttributeMaxDynamicSharedMemorySize, GEMM_SMEM);
    cudaFuncSetAttribute(tc_gemm<true, 4>,  cudaFuncAttributeMaxDynamicSharedMemorySize, GEMM_SMEM);

    const int grid_n   = (NNODES + 127) / 128;                 // 782
    const int rn       = RREL * NNODES;
    const int re       = RREL * EEDGES;
    const int scat_blk = (re * 32 + 255) / 256;
    const size_t agg_f4 = (size_t)RREL * NNODES * DDIM / 4;
    const size_t nd = (size_t)NNODES * DDIM;

    // degrees (topology-only: once)
    zero_int_kernel<<<(rn + 255) / 256, 256>>>(deg, rn);
    deg_count_kernel<<<(re + 255) / 256, 256>>>(edge_dst, deg);
    make_rdeg_kernel<<<(rn + 255) / 256, 256>>>(deg, rdeg);

    // projection: h0 = x @ proj_w + proj_b
    build_wt_proj<<<(128 * 128 + 255) / 256, 256>>>(proj_w, pwhi, pwlo);
    tc_gemm<false, 1><<<grid_n, 256, GEMM_SMEM>>>(x, x, x, x, pwhi, pwlo, proj_b, h0, NNODES);

    // ---- layer 1 ----
    build_wt_layer<<<(128 * 512 + 255) / 256, 256>>>(basis1, coeff1, loop1, wthi, wtlo);
    zero_f4_kernel<<<4096, 256>>>((float4*)agg, agg_f4);
    scatter_kernel<<<scat_blk, 256>>>(h0, edge_src, edge_dst, rdeg, agg);
    tc_gemm<true, 4><<<grid_n, 256, GEMM_SMEM>>>(agg, agg + nd, agg + 2 * nd, h0,
                                                 wthi, wtlo, bias1, h1, NNODES);

    // ---- layer 2 ----
    build_wt_layer<<<(128 * 512 + 255) / 256, 256>>>(basis2, coeff2, loop2, wthi, wtlo);
    zero_f4_kernel<<<4096, 256>>>((float4*)agg, agg_f4);
    scatter_kernel<<<scat_blk, 256>>>(h1, edge_src, edge_dst, rdeg, agg);
    tc_gemm<true, 4><<<grid_n, 256, GEMM_SMEM>>>(agg, agg + nd, agg + 2 * nd, h1,
                                                 wthi, wtlo, bias2, out, NNODES);
}

// round 4
// speedup vs baseline: 1.6477x; 1.2560x over previous
#include <cuda_runtime.h>
#include <cuda_bf16.h>
#include <cstdint>

// Problem constants
#define NNODES 100000
#define DDIM   128
#define RREL   3
#define EEDGES 500000
#define NBASIS 2

// ---------------- scratch (device globals) ----------------------------------
__device__ float g_h0[(size_t)NNODES * DDIM];
__device__ float g_h1[(size_t)NNODES * DDIM];
__device__ float g_agg[(size_t)RREL * NNODES * DDIM];
__device__ float g_rdeg[(size_t)RREL * NNODES];
__device__ int   g_deg [(size_t)RREL * NNODES];
__device__ __nv_bfloat16 g_wthi[128 * 512];   // layer weights, [o][k], hi part
__device__ __nv_bfloat16 g_wtlo[128 * 512];   // lo part
__device__ __nv_bfloat16 g_pwhi[128 * 128];   // proj weights [o][k], hi
__device__ __nv_bfloat16 g_pwlo[128 * 128];   // lo

// ---------------- smem layout for the GEMM -----------------------------------
// A: fp32 staging, 128 rows x 64 cols, pitch 72 floats (288B) -> conflict-free
//    LDS.64 fragment loads ((8g+2tg)%32 distinct within each 16-lane phase).
// B: bf16 hi/lo tiles, 128 rows x 64 cols, pitch 144B -> conflict-free LDS.32.
#define A_PITCH_F 72
#define A_PITCH_BYTES (A_PITCH_F * 4)          // 288
#define A_TILE (128 * A_PITCH_BYTES)           // 36864
#define B_PITCH 144
#define B_TILE (128 * B_PITCH)                 // 18432
#define OFF_A0 0
#define OFF_A1 (A_TILE)
#define OFF_BHI (2 * A_TILE)
#define OFF_BLO (2 * A_TILE + B_TILE)
#define GEMM_SMEM (2 * A_TILE + 2 * B_TILE)    // 110592

__device__ __forceinline__ uint32_t smem_u32(const void* p) {
    uint32_t a;
    asm("{ .reg .u64 t; cvta.to.shared.u64 t, %1; cvt.u32.u64 %0, t; }" : "=r"(a) : "l"(p));
    return a;
}

__device__ __forceinline__ void cp_async16(uint32_t dst, const void* src, uint32_t sz) {
    asm volatile("cp.async.cg.shared.global [%0], [%1], 16, %2;"
                 :: "r"(dst), "l"(src), "r"(sz));
}
#define CP_COMMIT()  asm volatile("cp.async.commit_group;" ::: "memory")
#define CP_WAIT(n)   asm volatile("cp.async.wait_group %0;" :: "n"(n) : "memory")

__device__ __forceinline__ void mma16816(float* c, const uint32_t* a, const uint32_t* b) {
    asm volatile(
        "mma.sync.aligned.m16n8k16.row.col.f32.bf16.bf16.f32 "
        "{%0,%1,%2,%3}, {%4,%5,%6,%7}, {%8,%9}, {%0,%1,%2,%3};\n"
        : "+f"(c[0]), "+f"(c[1]), "+f"(c[2]), "+f"(c[3])
        : "r"(a[0]), "r"(a[1]), "r"(a[2]), "r"(a[3]), "r"(b[0]), "r"(b[1]));
}

// fp32 pair -> packed bf16x2 hi + packed bf16x2 residual(lo)
__device__ __forceinline__ void split2(float2 f, uint32_t& h, uint32_t& l) {
    uint32_t hh;
    asm("cvt.rn.bf16x2.f32 %0, %1, %2;" : "=r"(hh) : "f"(f.y), "f"(f.x));
    float h0 = __uint_as_float(hh << 16);
    float h1 = __uint_as_float(hh & 0xffff0000u);
    asm("cvt.rn.bf16x2.f32 %0, %1, %2;" : "=r"(l) : "f"(f.y - h1), "f"(f.x - h0));
    h = hh;
}

// ---------------- split-bf16 tensor-core GEMM (cp.async pipelined) ------------
// C[n,o] = act( sum_s sum_k A_s[n,k] * W[s*128+k, o] + bias[o] )
// whi/wlo: [o][KSTRIDE] bf16 (pre-transposed + split), KSTRIDE = NSEG*128.
template <bool RELU, int NSEG>
__global__ __launch_bounds__(256, 2)
void tc_gemm(const float* __restrict__ A0, const float* __restrict__ A1,
             const float* __restrict__ A2, const float* __restrict__ A3,
             const __nv_bfloat16* __restrict__ whi, const __nv_bfloat16* __restrict__ wlo,
             const float* __restrict__ bias, float* __restrict__ C, int nrows) {
    extern __shared__ char smem[];
    const uint32_t sbase = smem_u32(smem);
    const int tid  = threadIdx.x;
    const int wid  = tid >> 5;
    const int lane = tid & 31;
    const int wm = wid & 3;          // warp row (4) -> 32 rows each
    const int wn = wid >> 2;         // warp col (2) -> 64 cols each
    const int g  = lane >> 2;        // 0..7
    const int tg = lane & 3;         // 0..3
    const int n0 = blockIdx.x * 128;
    const int KSTRIDE = NSEG * 128;
    const float* Aseg[4] = {A0, A1, A2, A3};
    const int NCHUNK = 2 * NSEG;

    float acc[2][8][4];
#pragma unroll
    for (int mt = 0; mt < 2; mt++)
#pragma unroll
        for (int nt = 0; nt < 8; nt++)
#pragma unroll
            for (int j = 0; j < 4; j++) acc[mt][nt][j] = 0.f;

    // ---- async A-chunk loader: chunk index cc -> Abuf[cc&1] ----
    auto load_A = [&](int cc) {
        const float* A = Aseg[cc >> 1];
        const int kc = (cc & 1) * 64;
        uint32_t dbase = sbase + ((cc & 1) ? OFF_A1 : OFF_A0);
#pragma unroll
        for (int i = 0; i < 8; ++i) {
            int idx = i * 256 + tid;       // 0..2047 16B transfers
            int row = idx >> 4;
            int q   = idx & 15;
            int n = n0 + row;
            bool valid = (n < nrows);
            const float* src = A + (size_t)(valid ? n : 0) * DDIM + kc + q * 4;
            cp_async16(dbase + row * A_PITCH_BYTES + q * 16, src, valid ? 16u : 0u);
        }
    };

    auto load_B = [&](int cc) {
#pragma unroll
        for (int i = 0; i < 4; ++i) {
            int idx = i * 256 + tid;       // 0..1023
            int n = idx >> 3;              // 8 x 16B per row
            int q = idx & 7;
            uint32_t boff = n * B_PITCH + q * 16;
            size_t goff = (size_t)n * KSTRIDE + cc * 64 + q * 8;
            cp_async16(sbase + OFF_BHI + boff, whi + goff, 16);
            cp_async16(sbase + OFF_BLO + boff, wlo + goff, 16);
        }
    };

    const int arow_f = (wm * 32 + g) * A_PITCH_F + 2 * tg;   // float index base
    const int brow   = (wn * 64 + g) * B_PITCH + tg * 4;     // byte offset base

    load_A(0);
    CP_COMMIT();

#pragma unroll 1
    for (int c = 0; c < NCHUNK; ++c) {
        load_B(c);
        CP_COMMIT();
        if (c + 1 < NCHUNK) {
            load_A(c + 1);
            CP_COMMIT();
            CP_WAIT(1);            // A_c + B_c complete; A_{c+1} in flight
        } else {
            CP_WAIT(0);
        }
        __syncthreads();

        const char* Ab = smem + ((c & 1) ? OFF_A1 : OFF_A0);

#pragma unroll
        for (int ks = 0; ks < 4; ++ks) {
            uint32_t ahi[2][4], alo[2][4], bfr[8][2];
#pragma unroll
            for (int mt = 0; mt < 2; ++mt) {
                int fb = arow_f + mt * 16 * A_PITCH_F + ks * 16;   // float idx
                float2 f0 = *reinterpret_cast<const float2*>(Ab + fb * 4);
                float2 f1 = *reinterpret_cast<const float2*>(Ab + (fb + 8 * A_PITCH_F) * 4);
                float2 f2 = *reinterpret_cast<const float2*>(Ab + (fb + 8) * 4);
                float2 f3 = *reinterpret_cast<const float2*>(Ab + (fb + 8 * A_PITCH_F + 8) * 4);
                split2(f0, ahi[mt][0], alo[mt][0]);
                split2(f1, ahi[mt][1], alo[mt][1]);
                split2(f2, ahi[mt][2], alo[mt][2]);
                split2(f3, ahi[mt][3], alo[mt][3]);
            }
#pragma unroll
            for (int nt = 0; nt < 8; ++nt) {
                int bb = brow + nt * (8 * B_PITCH) + ks * 32;
                bfr[nt][0] = *(const uint32_t*)(smem + OFF_BHI + bb);
                bfr[nt][1] = *(const uint32_t*)(smem + OFF_BHI + bb + 16);
            }
#pragma unroll
            for (int mt = 0; mt < 2; ++mt)
#pragma unroll
                for (int nt = 0; nt < 8; ++nt) {
                    mma16816(acc[mt][nt], ahi[mt], bfr[nt]);   // hi*hi
                    mma16816(acc[mt][nt], alo[mt], bfr[nt]);   // lo*hi
                }
#pragma unroll
            for (int nt = 0; nt < 8; ++nt) {
                int bb = brow + nt * (8 * B_PITCH) + ks * 32;
                bfr[nt][0] = *(const uint32_t*)(smem + OFF_BLO + bb);
                bfr[nt][1] = *(const uint32_t*)(smem + OFF_BLO + bb + 16);
            }
#pragma unroll
            for (int mt = 0; mt < 2; ++mt)
#pragma unroll
                for (int nt = 0; nt < 8; ++nt)
                    mma16816(acc[mt][nt], ahi[mt], bfr[nt]);   // hi*lo
        }
        __syncthreads();
    }

    // ---- epilogue: bias + relu, float2 stores ----
#pragma unroll
    for (int nt = 0; nt < 8; ++nt) {
        int col = wn * 64 + nt * 8 + 2 * tg;
        float bz0 = __ldg(bias + col);
        float bz1 = __ldg(bias + col + 1);
#pragma unroll
        for (int mt = 0; mt < 2; ++mt) {
            int row0 = n0 + wm * 32 + mt * 16 + g;
            int row1 = row0 + 8;
            float v0 = acc[mt][nt][0] + bz0, v1 = acc[mt][nt][1] + bz1;
            float v2 = acc[mt][nt][2] + bz0, v3 = acc[mt][nt][3] + bz1;
            if (RELU) {
                v0 = fmaxf(v0, 0.f); v1 = fmaxf(v1, 0.f);
                v2 = fmaxf(v2, 0.f); v3 = fmaxf(v3, 0.f);
            }
            if (row0 < nrows)
                *reinterpret_cast<float2*>(C + (size_t)row0 * DDIM + col) = make_float2(v0, v1);
            if (row1 < nrows)
                *reinterpret_cast<float2*>(C + (size_t)row1 * DDIM + col) = make_float2(v2, v3);
        }
    }
}

// ---------------- small utility kernels --------------------------------------
__global__ void zero_int_kernel(int* p, int n) {
    int i = blockIdx.x * blockDim.x + threadIdx.x;
    if (i < n) p[i] = 0;
}

__global__ void zero_f4_kernel(float4* p, size_t n4) {
    size_t i = (size_t)blockIdx.x * blockDim.x + threadIdx.x;
    size_t stride = (size_t)gridDim.x * blockDim.x;
    float4 z = make_float4(0.f, 0.f, 0.f, 0.f);
    for (; i < n4; i += stride) p[i] = z;
}

__global__ void deg_count_kernel(const int* __restrict__ dst, int* __restrict__ deg) {
    int i = blockIdx.x * blockDim.x + threadIdx.x;
    if (i >= RREL * EEDGES) return;
    int r = i / EEDGES;
    atomicAdd(&deg[r * NNODES + dst[i]], 1);
}

__global__ void make_rdeg_kernel(const int* __restrict__ deg, float* __restrict__ rdeg) {
    int i = blockIdx.x * blockDim.x + threadIdx.x;
    if (i >= RREL * NNODES) return;
    rdeg[i] = 1.0f / fmaxf((float)deg[i], 1.0f);
}

// Build stacked, transposed, bf16-split weights for a layer: wt[o][k], k in [0,512)
__global__ void build_wt_layer(const float* __restrict__ basis, const float* __restrict__ coeff,
                               const float* __restrict__ loopw,
                               __nv_bfloat16* __restrict__ whi, __nv_bfloat16* __restrict__ wlo) {
    int i = blockIdx.x * blockDim.x + threadIdx.x;   // 128*512
    if (i >= 128 * 512) return;
    int o = i >> 9;
    int k = i & 511;
    int seg = k >> 7;
    int kk = k & 127;
    float v;
    if (seg < 3)
        v = coeff[seg * NBASIS + 0] * basis[kk * DDIM + o]
          + coeff[seg * NBASIS + 1] * basis[DDIM * DDIM + kk * DDIM + o];
    else
        v = loopw[kk * DDIM + o];
    __nv_bfloat16 h = __float2bfloat16(v);
    whi[i] = h;
    wlo[i] = __float2bfloat16(v - __bfloat162float(h));
}

__global__ void build_wt_proj(const float* __restrict__ projw,
                              __nv_bfloat16* __restrict__ whi, __nv_bfloat16* __restrict__ wlo) {
    int i = blockIdx.x * blockDim.x + threadIdx.x;   // 128*128
    if (i >= 128 * 128) return;
    int o = i >> 7;
    int k = i & 127;
    float v = projw[k * DDIM + o];
    __nv_bfloat16 h = __float2bfloat16(v);
    whi[i] = h;
    wlo[i] = __float2bfloat16(v - __bfloat162float(h));
}

// ---------------- scatter-aggregate: one warp per edge ------------------------
__global__ void scatter_kernel(const float* __restrict__ h,
                               const int*   __restrict__ src,
                               const int*   __restrict__ dst,
                               const float* __restrict__ rdeg,
                               float* __restrict__ agg) {
    unsigned gw = ((unsigned)blockIdx.x * 256u + threadIdx.x) >> 5;
    int lane = threadIdx.x & 31;
    if (gw >= (unsigned)(RREL * EEDGES)) return;
    int r = (int)(gw / EEDGES);
    int s = __ldg(src + gw);
    int d = __ldg(dst + gw);
    float w = __ldg(rdeg + (size_t)r * NNODES + d);
    float4 v = *reinterpret_cast<const float4*>(h + (size_t)s * DDIM + lane * 4);
    float* p = agg + ((size_t)r * NNODES + d) * DDIM + lane * 4;
    asm volatile("red.global.add.v4.f32 [%0], {%1,%2,%3,%4};"
                 :: "l"(p), "f"(v.x * w), "f"(v.y * w), "f"(v.z * w), "f"(v.w * w)
                 : "memory");
}

// ---------------- launch -------------------------------------------------------
extern "C" void kernel_launch(void* const* d_in, const int* in_sizes, int n_in,
                              void* d_out, int out_size) {
    const float* x        = (const float*)d_in[0];
    const int*   edge_src = (const int*)  d_in[1];
    const int*   edge_dst = (const int*)  d_in[2];
    const float* proj_w   = (const float*)d_in[3];
    const float* proj_b   = (const float*)d_in[4];
    const float* basis1   = (const float*)d_in[5];
    const float* coeff1   = (const float*)d_in[6];
    const float* bias1    = (const float*)d_in[7];
    const float* loop1    = (const float*)d_in[8];
    const float* basis2   = (const float*)d_in[9];
    const float* coeff2   = (const float*)d_in[10];
    const float* bias2    = (const float*)d_in[11];
    const float* loop2    = (const float*)d_in[12];
    float* out = (float*)d_out;

    float *h0, *h1, *agg, *rdeg;
    int* deg;
    __nv_bfloat16 *wthi, *wtlo, *pwhi, *pwlo;
    cudaGetSymbolAddress((void**)&h0,   g_h0);
    cudaGetSymbolAddress((void**)&h1,   g_h1);
    cudaGetSymbolAddress((void**)&agg,  g_agg);
    cudaGetSymbolAddress((void**)&rdeg, g_rdeg);
    cudaGetSymbolAddress((void**)&deg,  g_deg);
    cudaGetSymbolAddress((void**)&wthi, g_wthi);
    cudaGetSymbolAddress((void**)&wtlo, g_wtlo);
    cudaGetSymbolAddress((void**)&pwhi, g_pwhi);
    cudaGetSymbolAddress((void**)&pwlo, g_pwlo);

    cudaFuncSetAttribute(tc_gemm<false, 1>, cudaFuncAttributeMaxDynamicSharedMemorySize, GEMM_SMEM);
    cudaFuncSetAttribute(tc_gemm<true, 4>,  cudaFuncAttributeMaxDynamicSharedMemorySize, GEMM_SMEM);

    const int grid_n   = (NNODES + 127) / 128;                 // 782
    const int rn       = RREL * NNODES;
    const int re       = RREL * EEDGES;
    const int scat_blk = (re * 32 + 255) / 256;
    const size_t agg_f4 = (size_t)RREL * NNODES * DDIM / 4;
    const size_t nd = (size_t)NNODES * DDIM;

    // degrees (topology-only: once)
    zero_int_kernel<<<(rn + 255) / 256, 256>>>(deg, rn);
    deg_count_kernel<<<(re + 255) / 256, 256>>>(edge_dst, deg);
    make_rdeg_kernel<<<(rn + 255) / 256, 256>>>(deg, rdeg);

    // projection: h0 = x @ proj_w + proj_b
    build_wt_proj<<<(128 * 128 + 255) / 256, 256>>>(proj_w, pwhi, pwlo);
    tc_gemm<false, 1><<<grid_n, 256, GEMM_SMEM>>>(x, x, x, x, pwhi, pwlo, proj_b, h0, NNODES);

    // ---- layer 1 ----
    build_wt_layer<<<(128 * 512 + 255) / 256, 256>>>(basis1, coeff1, loop1, wthi, wtlo);
    zero_f4_kernel<<<4096, 256>>>((float4*)agg, agg_f4);
    scatter_kernel<<<scat_blk, 256>>>(h0, edge_src, edge_dst, rdeg, agg);
    tc_gemm<true, 4><<<grid_n, 256, GEMM_SMEM>>>(agg, agg + nd, agg + 2 * nd, h0,
                                                 wthi, wtlo, bias1, h1, NNODES);

    // ---- layer 2 ----
    build_wt_layer<<<(128 * 512 + 255) / 256, 256>>>(basis2, coeff2, loop2, wthi, wtlo);
    zero_f4_kernel<<<4096, 256>>>((float4*)agg, agg_f4);
    scatter_kernel<<<scat_blk, 256>>>(h1, edge_src, edge_dst, rdeg, agg);
    tc_gemm<true, 4><<<grid_n, 256, GEMM_SMEM>>>(agg, agg + nd, agg + 2 * nd, h1,
                                                 wthi, wtlo, bias2, out, NNODES);
}

// round 5
// speedup vs baseline: 2.9507x; 1.7908x over previous
#include <cuda_runtime.h>
#include <cuda_bf16.h>
#include <cstdint>

// Problem constants
#define NNODES 100000
#define DDIM   128
#define RREL   3
#define EEDGES 500000
#define NBASIS 2
#define RN     (RREL * NNODES)
#define RE     (RREL * EEDGES)

// ---------------- scratch (device globals) ----------------------------------
__device__ float g_h0[(size_t)NNODES * DDIM];
__device__ float g_h1[(size_t)NNODES * DDIM];
__device__ float g_c0[(size_t)NNODES * DDIM];   // combo basis-0
__device__ float g_c1[(size_t)NNODES * DDIM];   // combo basis-1
__device__ float g_rdeg[RN];
__device__ int   g_deg [RN];
__device__ int   g_off [RN + 1];
__device__ int   g_cur [RN];
__device__ int   g_part[1024];
__device__ int   g_csr [RE];
__device__ __nv_bfloat16 g_wthi[128 * 384];   // layer weights [o][k], hi
__device__ __nv_bfloat16 g_wtlo[128 * 384];   // lo
__device__ __nv_bfloat16 g_pwhi[128 * 128];   // proj weights [o][k], hi
__device__ __nv_bfloat16 g_pwlo[128 * 128];   // lo

// ---------------- smem layout for the GEMM -----------------------------------
#define A_PITCH_F 72
#define A_PITCH_BYTES (A_PITCH_F * 4)          // 288
#define A_TILE (128 * A_PITCH_BYTES)           // 36864
#define B_PITCH 144
#define B_TILE (128 * B_PITCH)                 // 18432
#define OFF_A0 0
#define OFF_A1 (A_TILE)
#define OFF_BHI (2 * A_TILE)
#define OFF_BLO (2 * A_TILE + B_TILE)
#define GEMM_SMEM (2 * A_TILE + 2 * B_TILE)    // 110592

__device__ __forceinline__ uint32_t smem_u32(const void* p) {
    uint32_t a;
    asm("{ .reg .u64 t; cvta.to.shared.u64 t, %1; cvt.u32.u64 %0, t; }" : "=r"(a) : "l"(p));
    return a;
}

__device__ __forceinline__ void cp_async16(uint32_t dst, const void* src, uint32_t sz) {
    asm volatile("cp.async.cg.shared.global [%0], [%1], 16, %2;"
                 :: "r"(dst), "l"(src), "r"(sz));
}
#define CP_COMMIT()  asm volatile("cp.async.commit_group;" ::: "memory")
#define CP_WAIT(n)   asm volatile("cp.async.wait_group %0;" :: "n"(n) : "memory")

__device__ __forceinline__ void mma16816(float* c, const uint32_t* a, const uint32_t* b) {
    asm volatile(
        "mma.sync.aligned.m16n8k16.row.col.f32.bf16.bf16.f32 "
        "{%0,%1,%2,%3}, {%4,%5,%6,%7}, {%8,%9}, {%0,%1,%2,%3};\n"
        : "+f"(c[0]), "+f"(c[1]), "+f"(c[2]), "+f"(c[3])
        : "r"(a[0]), "r"(a[1]), "r"(a[2]), "r"(a[3]), "r"(b[0]), "r"(b[1]));
}

// fp32 pair -> packed bf16x2 hi + packed bf16x2 residual(lo)
__device__ __forceinline__ void split2(float2 f, uint32_t& h, uint32_t& l) {
    uint32_t hh;
    asm("cvt.rn.bf16x2.f32 %0, %1, %2;" : "=r"(hh) : "f"(f.y), "f"(f.x));
    float h0 = __uint_as_float(hh << 16);
    float h1 = __uint_as_float(hh & 0xffff0000u);
    asm("cvt.rn.bf16x2.f32 %0, %1, %2;" : "=r"(l) : "f"(f.y - h1), "f"(f.x - h0));
    h = hh;
}

// ---------------- split-bf16 tensor-core GEMM (cp.async pipelined) ------------
template <bool RELU, int NSEG>
__global__ __launch_bounds__(256, 2)
void tc_gemm(const float* __restrict__ A0, const float* __restrict__ A1,
             const float* __restrict__ A2,
             const __nv_bfloat16* __restrict__ whi, const __nv_bfloat16* __restrict__ wlo,
             const float* __restrict__ bias, float* __restrict__ C, int nrows) {
    extern __shared__ char smem[];
    const uint32_t sbase = smem_u32(smem);
    const int tid  = threadIdx.x;
    const int wid  = tid >> 5;
    const int lane = tid & 31;
    const int wm = wid & 3;
    const int wn = wid >> 2;
    const int g  = lane >> 2;
    const int tg = lane & 3;
    const int n0 = blockIdx.x * 128;
    const int KSTRIDE = NSEG * 128;
    const float* Aseg[3] = {A0, A1, A2};
    const int NCHUNK = 2 * NSEG;

    float acc[2][8][4];
#pragma unroll
    for (int mt = 0; mt < 2; mt++)
#pragma unroll
        for (int nt = 0; nt < 8; nt++)
#pragma unroll
            for (int j = 0; j < 4; j++) acc[mt][nt][j] = 0.f;

    auto load_A = [&](int cc) {
        const float* A = Aseg[cc >> 1];
        const int kc = (cc & 1) * 64;
        uint32_t dbase = sbase + ((cc & 1) ? OFF_A1 : OFF_A0);
#pragma unroll
        for (int i = 0; i < 8; ++i) {
            int idx = i * 256 + tid;
            int row = idx >> 4;
            int q   = idx & 15;
            int n = n0 + row;
            bool valid = (n < nrows);
            const float* src = A + (size_t)(valid ? n : 0) * DDIM + kc + q * 4;
            cp_async16(dbase + row * A_PITCH_BYTES + q * 16, src, valid ? 16u : 0u);
        }
    };

    auto load_B = [&](int cc) {
#pragma unroll
        for (int i = 0; i < 4; ++i) {
            int idx = i * 256 + tid;
            int n = idx >> 3;
            int q = idx & 7;
            uint32_t boff = n * B_PITCH + q * 16;
            size_t goff = (size_t)n * KSTRIDE + cc * 64 + q * 8;
            cp_async16(sbase + OFF_BHI + boff, whi + goff, 16);
            cp_async16(sbase + OFF_BLO + boff, wlo + goff, 16);
        }
    };

    const int arow_f = (wm * 32 + g) * A_PITCH_F + 2 * tg;
    const int brow   = (wn * 64 + g) * B_PITCH + tg * 4;

    load_A(0);
    CP_COMMIT();

#pragma unroll 1
    for (int c = 0; c < NCHUNK; ++c) {
        load_B(c);
        CP_COMMIT();
        if (c + 1 < NCHUNK) {
            load_A(c + 1);
            CP_COMMIT();
            CP_WAIT(1);
        } else {
            CP_WAIT(0);
        }
        __syncthreads();

        const char* Ab = smem + ((c & 1) ? OFF_A1 : OFF_A0);

#pragma unroll
        for (int ks = 0; ks < 4; ++ks) {
            uint32_t ahi[2][4], alo[2][4], bfr[8][2];
#pragma unroll
            for (int mt = 0; mt < 2; ++mt) {
                int fb = arow_f + mt * 16 * A_PITCH_F + ks * 16;
                float2 f0 = *reinterpret_cast<const float2*>(Ab + fb * 4);
                float2 f1 = *reinterpret_cast<const float2*>(Ab + (fb + 8 * A_PITCH_F) * 4);
                float2 f2 = *reinterpret_cast<const float2*>(Ab + (fb + 8) * 4);
                float2 f3 = *reinterpret_cast<const float2*>(Ab + (fb + 8 * A_PITCH_F + 8) * 4);
                split2(f0, ahi[mt][0], alo[mt][0]);
                split2(f1, ahi[mt][1], alo[mt][1]);
                split2(f2, ahi[mt][2], alo[mt][2]);
                split2(f3, ahi[mt][3], alo[mt][3]);
            }
#pragma unroll
            for (int nt = 0; nt < 8; ++nt) {
                int bb = brow + nt * (8 * B_PITCH) + ks * 32;
                bfr[nt][0] = *(const uint32_t*)(smem + OFF_BHI + bb);
                bfr[nt][1] = *(const uint32_t*)(smem + OFF_BHI + bb + 16);
            }
#pragma unroll
            for (int mt = 0; mt < 2; ++mt)
#pragma unroll
                for (int nt = 0; nt < 8; ++nt) {
                    mma16816(acc[mt][nt], ahi[mt], bfr[nt]);   // hi*hi
                    mma16816(acc[mt][nt], alo[mt], bfr[nt]);   // lo*hi
                }
#pragma unroll
            for (int nt = 0; nt < 8; ++nt) {
                int bb = brow + nt * (8 * B_PITCH) + ks * 32;
                bfr[nt][0] = *(const uint32_t*)(smem + OFF_BLO + bb);
                bfr[nt][1] = *(const uint32_t*)(smem + OFF_BLO + bb + 16);
            }
#pragma unroll
            for (int mt = 0; mt < 2; ++mt)
#pragma unroll
                for (int nt = 0; nt < 8; ++nt)
                    mma16816(acc[mt][nt], ahi[mt], bfr[nt]);   // hi*lo
        }
        __syncthreads();
    }

    // ---- epilogue ----
#pragma unroll
    for (int nt = 0; nt < 8; ++nt) {
        int col = wn * 64 + nt * 8 + 2 * tg;
        float bz0 = __ldg(bias + col);
        float bz1 = __ldg(bias + col + 1);
#pragma unroll
        for (int mt = 0; mt < 2; ++mt) {
            int row0 = n0 + wm * 32 + mt * 16 + g;
            int row1 = row0 + 8;
            float v0 = acc[mt][nt][0] + bz0, v1 = acc[mt][nt][1] + bz1;
            float v2 = acc[mt][nt][2] + bz0, v3 = acc[mt][nt][3] + bz1;
            if (RELU) {
                v0 = fmaxf(v0, 0.f); v1 = fmaxf(v1, 0.f);
                v2 = fmaxf(v2, 0.f); v3 = fmaxf(v3, 0.f);
            }
            if (row0 < nrows)
                *reinterpret_cast<float2*>(C + (size_t)row0 * DDIM + col) = make_float2(v0, v1);
            if (row1 < nrows)
                *reinterpret_cast<float2*>(C + (size_t)row1 * DDIM + col) = make_float2(v2, v3);
        }
    }
}

// ---------------- CSR construction -------------------------------------------
__global__ void zero_int_kernel(int* p, int n) {
    int i = blockIdx.x * blockDim.x + threadIdx.x;
    if (i < n) p[i] = 0;
}

__global__ void deg_count_kernel(const int* __restrict__ dst, int* __restrict__ deg) {
    int i = blockIdx.x * blockDim.x + threadIdx.x;
    if (i >= RE) return;
    int r = i / EEDGES;
    atomicAdd(&deg[r * NNODES + dst[i]], 1);
}

// k1: per-block (1024 elems) reduce
__global__ void scan_reduce(const int* __restrict__ deg, int* __restrict__ part, int n) {
    __shared__ int sm[256];
    int b = blockIdx.x, t = threadIdx.x;
    int i0 = b * 1024 + t * 4;
    int s = 0;
#pragma unroll
    for (int j = 0; j < 4; ++j) { int i = i0 + j; if (i < n) s += deg[i]; }
    sm[t] = s; __syncthreads();
    for (int st = 128; st > 0; st >>= 1) { if (t < st) sm[t] += sm[t + st]; __syncthreads(); }
    if (t == 0) part[b] = sm[0];
}

// k2: single-block exclusive scan of partials (n <= 512)
__global__ void scan_partials(int* part, int n) {
    __shared__ int sm[512];
    int t = threadIdx.x;
    int v = (t < n) ? part[t] : 0;
    sm[t] = v; __syncthreads();
    for (int s = 1; s < 512; s <<= 1) {
        int add = (t >= s) ? sm[t - s] : 0;
        __syncthreads();
        sm[t] += add;
        __syncthreads();
    }
    if (t < n) part[t] = sm[t] - v;
}

// k3: final exclusive scan -> off, cur
__global__ void scan_final(const int* __restrict__ deg, const int* __restrict__ part,
                           int* __restrict__ off, int* __restrict__ cur, int n) {
    __shared__ int sm[256];
    int b = blockIdx.x, t = threadIdx.x;
    int i0 = b * 1024 + t * 4;
    int v[4]; int s = 0;
#pragma unroll
    for (int j = 0; j < 4; ++j) { int i = i0 + j; v[j] = (i < n) ? deg[i] : 0; s += v[j]; }
    sm[t] = s; __syncthreads();
    for (int st = 1; st < 256; st <<= 1) {
        int add = (t >= st) ? sm[t - st] : 0;
        __syncthreads();
        sm[t] += add;
        __syncthreads();
    }
    int base = part[b] + sm[t] - s;
#pragma unroll
    for (int j = 0; j < 4; ++j) {
        int i = i0 + j;
        if (i < n) { off[i] = base; cur[i] = base; base += v[j]; }
    }
}

__global__ void make_rdeg_kernel(const int* __restrict__ deg, float* __restrict__ rdeg,
                                 int* __restrict__ off) {
    int i = blockIdx.x * blockDim.x + threadIdx.x;
    if (i == 0) off[RN] = RE;
    if (i >= RN) return;
    rdeg[i] = 1.0f / fmaxf((float)deg[i], 1.0f);
}

__global__ void fill_csr(const int* __restrict__ src, const int* __restrict__ dst,
                         int* __restrict__ cur, int* __restrict__ csr) {
    int i = blockIdx.x * blockDim.x + threadIdx.x;
    if (i >= RE) return;
    int r = i / EEDGES;
    int slot = atomicAdd(&cur[r * NNODES + dst[i]], 1);
    csr[slot] = src[i];
}

// ---------------- gather-aggregate into basis combos ---------------------------
// warp per dst node: combo_b[d] = sum_r coeff[r,b] * rdeg[r,d] * sum_{e in N_r(d)} h[src_e]
__global__ __launch_bounds__(256)
void gather_combo(const float* __restrict__ h, const int* __restrict__ off,
                  const int* __restrict__ csr, const float* __restrict__ rdeg,
                  const float* __restrict__ coeff,
                  float* __restrict__ c0, float* __restrict__ c1) {
    int gw = (int)(((unsigned)blockIdx.x * 256u + threadIdx.x) >> 5);
    int lane = threadIdx.x & 31;
    if (gw >= NNODES) return;
    float4 a0 = make_float4(0.f, 0.f, 0.f, 0.f);
    float4 a1 = a0;
#pragma unroll
    for (int r = 0; r < RREL; ++r) {
        int base = r * NNODES + gw;
        int s0 = __ldg(off + base), s1 = __ldg(off + base + 1);
        float4 sum = make_float4(0.f, 0.f, 0.f, 0.f);
        int e = s0;
        for (; e + 2 <= s1; e += 2) {
            int sa = __ldg(csr + e), sb = __ldg(csr + e + 1);
            float4 va = *reinterpret_cast<const float4*>(h + (size_t)sa * DDIM + lane * 4);
            float4 vb = *reinterpret_cast<const float4*>(h + (size_t)sb * DDIM + lane * 4);
            sum.x += va.x + vb.x; sum.y += va.y + vb.y;
            sum.z += va.z + vb.z; sum.w += va.w + vb.w;
        }
        if (e < s1) {
            int sa = __ldg(csr + e);
            float4 va = *reinterpret_cast<const float4*>(h + (size_t)sa * DDIM + lane * 4);
            sum.x += va.x; sum.y += va.y; sum.z += va.z; sum.w += va.w;
        }
        float w  = __ldg(rdeg + base);
        float k0 = __ldg(coeff + r * NBASIS)     * w;
        float k1 = __ldg(coeff + r * NBASIS + 1) * w;
        a0.x += k0 * sum.x; a0.y += k0 * sum.y; a0.z += k0 * sum.z; a0.w += k0 * sum.w;
        a1.x += k1 * sum.x; a1.y += k1 * sum.y; a1.z += k1 * sum.z; a1.w += k1 * sum.w;
    }
    *reinterpret_cast<float4*>(c0 + (size_t)gw * DDIM + lane * 4) = a0;
    *reinterpret_cast<float4*>(c1 + (size_t)gw * DDIM + lane * 4) = a1;
}

// ---------------- weight preparation -------------------------------------------
// Layer weights: wt[o][k], k in [0,384): seg 0 = basis0, seg 1 = basis1, seg 2 = loop
__global__ void build_wt_layer(const float* __restrict__ basis,
                               const float* __restrict__ loopw,
                               __nv_bfloat16* __restrict__ whi, __nv_bfloat16* __restrict__ wlo) {
    int i = blockIdx.x * blockDim.x + threadIdx.x;   // 128*384
    if (i >= 128 * 384) return;
    int o = i / 384;
    int k = i - o * 384;
    int seg = k >> 7;
    int kk = k & 127;
    float v;
    if (seg < 2)
        v = basis[(size_t)seg * DDIM * DDIM + kk * DDIM + o];
    else
        v = loopw[kk * DDIM + o];
    __nv_bfloat16 h = __float2bfloat16(v);
    whi[i] = h;
    wlo[i] = __float2bfloat16(v - __bfloat162float(h));
}

__global__ void build_wt_proj(const float* __restrict__ projw,
                              __nv_bfloat16* __restrict__ whi, __nv_bfloat16* __restrict__ wlo) {
    int i = blockIdx.x * blockDim.x + threadIdx.x;   // 128*128
    if (i >= 128 * 128) return;
    int o = i >> 7;
    int k = i & 127;
    float v = projw[k * DDIM + o];
    __nv_bfloat16 h = __float2bfloat16(v);
    whi[i] = h;
    wlo[i] = __float2bfloat16(v - __bfloat162float(h));
}

// ---------------- launch ----------------------------------------------------------
extern "C" void kernel_launch(void* const* d_in, const int* in_sizes, int n_in,
                              void* d_out, int out_size) {
    const float* x        = (const float*)d_in[0];
    const int*   edge_src = (const int*)  d_in[1];
    const int*   edge_dst = (const int*)  d_in[2];
    const float* proj_w   = (const float*)d_in[3];
    const float* proj_b   = (const float*)d_in[4];
    const float* basis1   = (const float*)d_in[5];
    const float* coeff1   = (const float*)d_in[6];
    const float* bias1    = (const float*)d_in[7];
    const float* loop1    = (const float*)d_in[8];
    const float* basis2   = (const float*)d_in[9];
    const float* coeff2   = (const float*)d_in[10];
    const float* bias2    = (const float*)d_in[11];
    const float* loop2    = (const float*)d_in[12];
    float* out = (float*)d_out;

    float *h0, *h1, *c0, *c1, *rdeg;
    int *deg, *off, *cur, *part, *csr;
    __nv_bfloat16 *wthi, *wtlo, *pwhi, *pwlo;
    cudaGetSymbolAddress((void**)&h0,   g_h0);
    cudaGetSymbolAddress((void**)&h1,   g_h1);
    cudaGetSymbolAddress((void**)&c0,   g_c0);
    cudaGetSymbolAddress((void**)&c1,   g_c1);
    cudaGetSymbolAddress((void**)&rdeg, g_rdeg);
    cudaGetSymbolAddress((void**)&deg,  g_deg);
    cudaGetSymbolAddress((void**)&off,  g_off);
    cudaGetSymbolAddress((void**)&cur,  g_cur);
    cudaGetSymbolAddress((void**)&part, g_part);
    cudaGetSymbolAddress((void**)&csr,  g_csr);
    cudaGetSymbolAddress((void**)&wthi, g_wthi);
    cudaGetSymbolAddress((void**)&wtlo, g_wtlo);
    cudaGetSymbolAddress((void**)&pwhi, g_pwhi);
    cudaGetSymbolAddress((void**)&pwlo, g_pwlo);

    cudaFuncSetAttribute(tc_gemm<false, 1>, cudaFuncAttributeMaxDynamicSharedMemorySize, GEMM_SMEM);
    cudaFuncSetAttribute(tc_gemm<true, 3>,  cudaFuncAttributeMaxDynamicSharedMemorySize, GEMM_SMEM);

    const int grid_n     = (NNODES + 127) / 128;             // 782
    const int scan_blks  = (RN + 1023) / 1024;               // 293
    const int gather_blk = (NNODES * 32 + 255) / 256;        // 12500

    // ---- CSR-transpose build (topology only, reused by both layers) ----
    zero_int_kernel<<<(RN + 255) / 256, 256>>>(deg, RN);
    deg_count_kernel<<<(RE + 255) / 256, 256>>>(edge_dst, deg);
    scan_reduce<<<scan_blks, 256>>>(deg, part, RN);
    scan_partials<<<1, 512>>>(part, scan_blks);
    scan_final<<<scan_blks, 256>>>(deg, part, off, cur, RN);
    make_rdeg_kernel<<<(RN + 255) / 256, 256>>>(deg, rdeg, off);
    fill_csr<<<(RE + 255) / 256, 256>>>(edge_src, edge_dst, cur, csr);

    // ---- projection ----
    build_wt_proj<<<(128 * 128 + 255) / 256, 256>>>(proj_w, pwhi, pwlo);
    tc_gemm<false, 1><<<grid_n, 256, GEMM_SMEM>>>(x, x, x, pwhi, pwlo, proj_b, h0, NNODES);

    // ---- layer 1 ----
    build_wt_layer<<<(128 * 384 + 255) / 256, 256>>>(basis1, loop1, wthi, wtlo);
    gather_combo<<<gather_blk, 256>>>(h0, off, csr, rdeg, coeff1, c0, c1);
    tc_gemm<true, 3><<<grid_n, 256, GEMM_SMEM>>>(c0, c1, h0, wthi, wtlo, bias1, h1, NNODES);

    // ---- layer 2 ----
    build_wt_layer<<<(128 * 384 + 255) / 256, 256>>>(basis2, loop2, wthi, wtlo);
    gather_combo<<<gather_blk, 256>>>(h1, off, csr, rdeg, coeff2, c0, c1);
    tc_gemm<true, 3><<<grid_n, 256, GEMM_SMEM>>>(c0, c1, h1, wthi, wtlo, bias2, out, NNODES);
}